// round 13
// baseline (speedup 1.0000x reference)
#include <cuda_runtime.h>
#include <cuda_fp16.h>
#include <math.h>
#include <stdint.h>

#define BB 4
#define HH 8
#define NN 2048
#define DD 512
#define DH 64
#define M_TOT (BB*NN)          // 8192
#define NQKV (3*DD)            // 1536
#define LOG2E 1.4426950408889634f

// ---------------- device scratch ----------------
__device__ __align__(16) __half g_xh [(size_t)M_TOT*DD];
__device__ __align__(16) __half g_wqh[(size_t)NQKV*DD];
__device__ __align__(16) __half g_woh[(size_t)DD*DD];
__device__ __align__(16) __half g_qkvh[(size_t)3*32*NN*DH];  // centered q,k,v
__device__ __align__(16) __half g_oh[(size_t)M_TOT*DD];      // centered attn out
__device__ float g_xsq[M_TOT];
__device__ float g_wqsq[NQKV];
__device__ float g_wosq[DD];
__device__ float g_wrs[DD];                          // row-sums of w_out
__device__ float g_osq[M_TOT];
__device__ __align__(16) float g_qksq[2*32*NN];      // centered |q|^2, |k|^2 per (bh,n)

// ---------------- helpers ----------------
__device__ __forceinline__ void ldmx4(uint32_t& r0,uint32_t& r1,uint32_t& r2,uint32_t& r3, const void* p){
    uint32_t a = (uint32_t)__cvta_generic_to_shared(p);
    asm volatile("ldmatrix.sync.aligned.m8n8.x4.shared.b16 {%0,%1,%2,%3}, [%4];"
        : "=r"(r0),"=r"(r1),"=r"(r2),"=r"(r3) : "r"(a));
}
__device__ __forceinline__ void ldmx4t(uint32_t& r0,uint32_t& r1,uint32_t& r2,uint32_t& r3, const void* p){
    uint32_t a = (uint32_t)__cvta_generic_to_shared(p);
    asm volatile("ldmatrix.sync.aligned.m8n8.x4.trans.shared.b16 {%0,%1,%2,%3}, [%4];"
        : "=r"(r0),"=r"(r1),"=r"(r2),"=r"(r3) : "r"(a));
}
// fp16-accumulate MMA: D,C are 2 x .f16x2 regs
__device__ __forceinline__ void mmaf16(uint32_t* c, const uint32_t* a, uint32_t b0, uint32_t b1){
    asm volatile("mma.sync.aligned.m16n8k16.row.col.f16.f16.f16.f16 "
        "{%0,%1}, {%2,%3,%4,%5}, {%6,%7}, {%0,%1};"
        : "+r"(c[0]),"+r"(c[1])
        : "r"(a[0]),"r"(a[1]),"r"(a[2]),"r"(a[3]),"r"(b0),"r"(b1));
}
__device__ __forceinline__ void cp_async16(void* dst, const void* src){
    uint32_t a = (uint32_t)__cvta_generic_to_shared(dst);
    asm volatile("cp.async.cg.shared.global [%0], [%1], 16;" :: "r"(a), "l"(src) : "memory");
}
#define CP_COMMIT  asm volatile("cp.async.commit_group;" ::: "memory")
template<int N> __device__ __forceinline__ void cp_wait(){
    asm volatile("cp.async.wait_group %0;" :: "n"(N) : "memory");
}
__device__ __forceinline__ uint32_t h2exp2(uint32_t t){
    uint32_t p; asm("ex2.approx.f16x2 %0, %1;" : "=r"(p) : "r"(t)); return p;
}

// ---------------- prep: fp16 convert + norms/rowsums, zero accumulators ----------------
__global__ void prep_kernel(const float* __restrict__ x, const float* __restrict__ wq,
                            const float* __restrict__ wo){
    int r = blockIdx.x;
    const float* src; __half* dstb; float* dsq; float* drs = nullptr;
    if (r < M_TOT)              { src = x  + (size_t)r*DD; dstb = g_xh  + (size_t)r*DD; dsq = g_xsq + r; }
    else if (r < M_TOT + NQKV)  { int rr = r - M_TOT; src = wq + (size_t)rr*DD; dstb = g_wqh + (size_t)rr*DD; dsq = g_wqsq + rr; }
    else { int rr = r - M_TOT - NQKV; src = wo + (size_t)rr*DD; dstb = g_woh + (size_t)rr*DD; dsq = g_wosq + rr; drs = g_wrs + rr; }

    if (r < 1024) g_qksq[r*128 + threadIdx.x] = 0.f;   // zero 2*32*2048 norm accumulators

    float4 v = ((const float4*)src)[threadIdx.x];
    __half2 h0 = __floats2half2_rn(v.x, v.y);
    __half2 h1 = __floats2half2_rn(v.z, v.w);
    __half2* d2 = (__half2*)(dstb + threadIdx.x*4);
    d2[0]=h0; d2[1]=h1;
    float2 f0 = __half22float2(h0), f1 = __half22float2(h1);
    float ss = f0.x*f0.x + f0.y*f0.y + f1.x*f1.x + f1.y*f1.y;
    float rs = f0.x + f0.y + f1.x + f1.y;
    #pragma unroll
    for (int o=16;o>0;o>>=1){ ss += __shfl_xor_sync(~0u, ss, o); rs += __shfl_xor_sync(~0u, rs, o); }
    __shared__ float wsum[4], wsum2[4];
    if ((threadIdx.x&31)==0){ wsum[threadIdx.x>>5]=ss; wsum2[threadIdx.x>>5]=rs; }
    __syncthreads();
    if (threadIdx.x==0){
        *dsq = wsum[0]+wsum[1]+wsum[2]+wsum[3];
        if (drs) *drs = wsum2[0]+wsum2[1]+wsum2[2]+wsum2[3];
        if (r < M_TOT) g_osq[r] = 0.f;
    }
}

// ========== GEMMs: 128 threads, 4 warps (2x2), warp tile 64x64, K-chunk 32, 3-stage ==========
// stage: A [128][40] half = 10240 B, B [128][40] half = 10240 B -> 20480 B/stage, 60 KB total
#define GST 20480
#define GSM_BYTES (3*GST)

// ---------------- QKV GEMM ----------------
__global__ __launch_bounds__(128,3) void qkv_gemm_tc(){
    extern __shared__ char smc[];
    int tid=threadIdx.x, lane=tid&31, wid=tid>>5;
    int wr=wid>>1, wc=wid&1;
    int m0=blockIdx.y*128, n0=blockIdx.x*128;
    uint32_t acc[4][8][2];
    #pragma unroll
    for(int i=0;i<4;i++) for(int j=0;j<8;j++){ acc[i][j][0]=0u; acc[i][j][1]=0u; }

    auto load_stage = [&](int kt, int st){
        __half* As = (__half*)(smc + st*GST);
        __half* Bs = (__half*)(smc + st*GST + 10240);
        #pragma unroll
        for (int u=0;u<4;u++){
            int idx=tid+128*u; int row=idx>>2; int q=idx&3;
            cp_async16(&As[row*40+q*8], &g_xh [(size_t)(m0+row)*DD + kt + q*8]);
            cp_async16(&Bs[row*40+q*8], &g_wqh[(size_t)(n0+row)*DD + kt + q*8]);
        }
    };
    load_stage(0, 0);  CP_COMMIT;
    load_stage(32, 1); CP_COMMIT;

    for (int it=0; it<16; it++){
        int st = it%3;
        if (it<15) cp_wait<1>(); else cp_wait<0>();
        __syncthreads();
        if (it+2 < 16){ load_stage((it+2)*32, (it+2)%3); CP_COMMIT; }
        __half* As = (__half*)(smc + st*GST);
        __half* Bs = (__half*)(smc + st*GST + 10240);
        #pragma unroll
        for (int kc=0;kc<2;kc++){
            uint32_t a[4][4];
            #pragma unroll
            for (int mt=0;mt<4;mt++)
                ldmx4(a[mt][0],a[mt][1],a[mt][2],a[mt][3],
                      &As[(wr*64+mt*16+(lane&15))*40 + kc*16 + (lane>>4)*8]);
            #pragma unroll
            for (int p=0;p<4;p++){
                uint32_t b0,b1,b2,b3;
                ldmx4(b0,b1,b2,b3,
                      &Bs[(wc*64+p*16+(lane>>4)*8+(lane&7))*40 + kc*16 + ((lane>>3)&1)*8]);
                #pragma unroll
                for (int mt=0;mt<4;mt++){
                    mmaf16(acc[mt][2*p],   a[mt], b0,b1);
                    mmaf16(acc[mt][2*p+1], a[mt], b2,b3);
                }
            }
        }
    }
    int colbase = n0 + wc*64;
    int part = colbase>>9, rem = colbase&511, h = rem>>6, dbase = rem&63;
    #pragma unroll
    for (int mt=0;mt<4;mt++){
        #pragma unroll
        for (int hh=0;hh<2;hh++){
            int m = m0 + wr*64 + mt*16 + (lane>>2) + 8*hh;
            int b = m>>11, n = m&2047;
            float xs = g_xsq[m];
            __half* orow = g_qkvh + ((size_t)(part*32 + b*8 + h)*NN + n)*DH;
            float ss = 0.f;
            #pragma unroll
            for (int nt=0;nt<8;nt++){
                int col = colbase + nt*8 + 2*(lane&3);
                float2 dd = __half22float2(*(__half2*)&acc[mt][nt][hh]);
                float v0 = sqrtf(fmaxf(xs + g_wqsq[col]   - 2.f*dd.x, 0.f)) - 32.f;
                float v1 = sqrtf(fmaxf(xs + g_wqsq[col+1] - 2.f*dd.y, 0.f)) - 32.f;
                __half2 h2 = __floats2half2_rn(v0, v1);
                *(__half2*)&orow[dbase + nt*8 + 2*(lane&3)] = h2;
                float2 rr = __half22float2(h2);           // norms from ROUNDED values
                ss += rr.x*rr.x + rr.y*rr.y;
            }
            if (part < 2){                                // q- AND k-norms
                ss += __shfl_xor_sync(~0u, ss, 1);
                ss += __shfl_xor_sync(~0u, ss, 2);
                if ((lane&3)==0) atomicAdd(&g_qksq[(part*32 + b*8 + h)*NN + n], ss);
            }
        }
    }
}

// ---------------- output GEMM ----------------
__global__ __launch_bounds__(128,3) void out_gemm_tc(float* __restrict__ out){
    extern __shared__ char smc[];
    int tid=threadIdx.x, lane=tid&31, wid=tid>>5;
    int wr=wid>>1, wc=wid&1;
    int m0=blockIdx.y*128, n0=blockIdx.x*128;
    uint32_t acc[4][8][2];
    #pragma unroll
    for(int i=0;i<4;i++) for(int j=0;j<8;j++){ acc[i][j][0]=0u; acc[i][j][1]=0u; }

    auto load_stage = [&](int kt, int st){
        __half* As = (__half*)(smc + st*GST);
        __half* Bs = (__half*)(smc + st*GST + 10240);
        #pragma unroll
        for (int u=0;u<4;u++){
            int idx=tid+128*u; int row=idx>>2; int q=idx&3;
            cp_async16(&As[row*40+q*8], &g_oh [(size_t)(m0+row)*DD + kt + q*8]);
            cp_async16(&Bs[row*40+q*8], &g_woh[(size_t)(n0+row)*DD + kt + q*8]);
        }
    };
    load_stage(0, 0);  CP_COMMIT;
    load_stage(32, 1); CP_COMMIT;

    for (int it=0; it<16; it++){
        int st = it%3;
        if (it<15) cp_wait<1>(); else cp_wait<0>();
        __syncthreads();
        if (it+2 < 16){ load_stage((it+2)*32, (it+2)%3); CP_COMMIT; }
        __half* As = (__half*)(smc + st*GST);
        __half* Bs = (__half*)(smc + st*GST + 10240);
        #pragma unroll
        for (int kc=0;kc<2;kc++){
            uint32_t a[4][4];
            #pragma unroll
            for (int mt=0;mt<4;mt++)
                ldmx4(a[mt][0],a[mt][1],a[mt][2],a[mt][3],
                      &As[(wr*64+mt*16+(lane&15))*40 + kc*16 + (lane>>4)*8]);
            #pragma unroll
            for (int p=0;p<4;p++){
                uint32_t b0,b1,b2,b3;
                ldmx4(b0,b1,b2,b3,
                      &Bs[(wc*64+p*16+(lane>>4)*8+(lane&7))*40 + kc*16 + ((lane>>3)&1)*8]);
                #pragma unroll
                for (int mt=0;mt<4;mt++){
                    mmaf16(acc[mt][2*p],   a[mt], b0,b1);
                    mmaf16(acc[mt][2*p+1], a[mt], b2,b3);
                }
            }
        }
    }
    #pragma unroll
    for (int mt=0;mt<4;mt++){
        #pragma unroll
        for (int hh=0;hh<2;hh++){
            int m = m0 + wr*64 + mt*16 + (lane>>2) + 8*hh;
            float os = g_osq[m];
            #pragma unroll
            for (int nt=0;nt<8;nt++){
                int col = n0 + wc*64 + nt*8 + 2*(lane&3);
                float2 dd = __half22float2(*(__half2*)&acc[mt][nt][hh]);
                float dot0 = dd.x + 32.f*g_wrs[col];
                float dot1 = dd.y + 32.f*g_wrs[col+1];
                out[(size_t)m*DD + col]   = sqrtf(fmaxf(os + g_wosq[col]   - 2.f*dot0, 0.f));
                out[(size_t)m*DD + col+1] = sqrtf(fmaxf(os + g_wosq[col+1] - 2.f*dot1, 0.f));
            }
        }
    }
}

// ---------- flash attention: 128 threads, 4 warps x 32 rows, fp16 end-to-end, 3-stage ring ----------
// smem: Qs [128][72] = 18432 | stage s at 18432+s*18688: K(9216) V(9216) ksq(256)
#define FSTAGE 18688
#define FSM_BYTES (18432 + 3*FSTAGE)
__global__ __launch_bounds__(128,3) void flash_tc(){
    extern __shared__ char smem[];
    __half* Qs = (__half*)smem;

    int tid=threadIdx.x, lane=tid&31, w=tid>>5;   // 4 warps
    int bh = blockIdx.y; int i0 = blockIdx.x*128;
    const __half* qg = g_qkvh + ((size_t)(0*32+bh)*NN + i0)*DH;
    const __half* kg = g_qkvh + (size_t)(1*32+bh)*NN*DH;
    const __half* vg = g_qkvh + (size_t)(2*32+bh)*NN*DH;
    const float* qsqg = g_qksq + (size_t)(0*32+bh)*NN + i0;
    const float* ksqg = g_qksq + (size_t)(1*32+bh)*NN;

    auto load_stage = [&](int j0, int st){
        char* base = smem + 18432 + st*FSTAGE;
        __half* Ks = (__half*)base;
        __half* Vs = (__half*)(base + 9216);
        float* kq = (float*)(base + 18432);
        #pragma unroll
        for (int u=0;u<4;u++){
            int idx=tid+128*u; int row=idx>>3; int q=idx&7;
            cp_async16(&Ks[row*72+q*8], &kg[(size_t)(j0+row)*DH+q*8]);
            cp_async16(&Vs[row*72+q*8], &vg[(size_t)(j0+row)*DH+q*8]);
        }
        if (tid<16) cp_async16(&kq[tid*4], &ksqg[j0+tid*4]);
    };

    #pragma unroll
    for (int u=0;u<8;u++){
        int idx=tid+128*u; int row=idx>>3; int q=idx&7;
        cp_async16(&Qs[row*72+q*8], &qg[(size_t)row*DH + q*8]);
    }
    CP_COMMIT;
    load_stage(0, 0);  CP_COMMIT;
    load_stage(64, 1); CP_COMMIT;

    cp_wait<2>();
    __syncthreads();

    // hoist Q fragments: warp w owns rows [32w, 32w+32), two 16-row m-tiles
    uint32_t qf[2][4][4];
    #pragma unroll
    for (int mt=0;mt<2;mt++)
        #pragma unroll
        for (int kc=0;kc<4;kc++)
            ldmx4(qf[mt][kc][0],qf[mt][kc][1],qf[mt][kc][2],qf[mt][kc][3],
                  &Qs[(w*32+mt*16+(lane&15))*72 + kc*16 + (lane>>4)*8]);

    const float C2 = 0.125f*LOG2E;
    const float BIAS = 12.0f;                 // logit = BIAS - C2*d^2 <= BIAS -> p <= 4096 (fp16-safe)
    const __half2 C1h = __float2half2_rn(0.25f*LOG2E);
    float rowc[2][2];
    #pragma unroll
    for (int mt=0;mt<2;mt++){
        rowc[mt][0] = BIAS - C2*qsqg[w*32 + mt*16 + (lane>>2)];
        rowc[mt][1] = BIAS - C2*qsqg[w*32 + mt*16 + (lane>>2) + 8];
    }

    float lr[2][2] = {{0.f,0.f},{0.f,0.f}};
    uint32_t accO[2][8][2];
    #pragma unroll
    for (int mt=0;mt<2;mt++) for (int j=0;j<8;j++){ accO[mt][j][0]=0u; accO[mt][j][1]=0u; }

    for (int t=0; t<32; t++){
        int st = t%3;
        if (t<31) cp_wait<1>(); else cp_wait<0>();
        __syncthreads();
        if (t+2 < 32){ load_stage((t+2)*64, (t+2)%3); CP_COMMIT; }
        char* base = smem + 18432 + st*FSTAGE;
        __half* Ks = (__half*)base;
        __half* Vs = (__half*)(base + 9216);
        const float* ksq = (const float*)(base + 18432);

        // S = Q.K^T (fp16 accum): 32 rows x 64 j per warp; K fragments shared across both m-tiles
        uint32_t s2[2][8][2];
        #pragma unroll
        for(int mt=0;mt<2;mt++) for(int j=0;j<8;j++){ s2[mt][j][0]=0u; s2[mt][j][1]=0u; }
        #pragma unroll
        for (int kc=0;kc<4;kc++){
            #pragma unroll
            for (int p=0;p<4;p++){
                uint32_t b0,b1,b2,b3;
                ldmx4(b0,b1,b2,b3,
                      &Ks[(p*16+(lane>>4)*8+(lane&7))*72 + kc*16 + ((lane>>3)&1)*8]);
                #pragma unroll
                for (int mt=0;mt<2;mt++){
                    mmaf16(s2[mt][2*p],   qf[mt][kc], b0,b1);
                    mmaf16(s2[mt][2*p+1], qf[mt][kc], b2,b3);
                }
            }
        }

        // p = exp2(C1*s + rowc - C2*|k|^2) in half2; result IS the PV A-fragment
        #pragma unroll
        for (int mt=0;mt<2;mt++){
            __half2 hs0 = __float2half2_rn(0.f), hs1 = __float2half2_rn(0.f);
            #pragma unroll
            for (int nt=0;nt<8;nt++){
                float2 kf = *(const float2*)&ksq[nt*8 + 2*(lane&3)];
                __half2 c0 = __floats2half2_rn(rowc[mt][0] - C2*kf.x, rowc[mt][0] - C2*kf.y);
                __half2 c1 = __floats2half2_rn(rowc[mt][1] - C2*kf.x, rowc[mt][1] - C2*kf.y);
                __half2 t0 = __hfma2(*(__half2*)&s2[mt][nt][0], C1h, c0);
                __half2 t1 = __hfma2(*(__half2*)&s2[mt][nt][1], C1h, c1);
                s2[mt][nt][0] = h2exp2(*(uint32_t*)&t0);
                s2[mt][nt][1] = h2exp2(*(uint32_t*)&t1);
                hs0 = __hadd2(hs0, *(__half2*)&s2[mt][nt][0]);
                hs1 = __hadd2(hs1, *(__half2*)&s2[mt][nt][1]);
            }
            float2 f0 = __half22float2(hs0), f1 = __half22float2(hs1);
            float rs0 = f0.x + f0.y, rs1 = f1.x + f1.y;
            rs0 += __shfl_xor_sync(~0u, rs0, 1); rs0 += __shfl_xor_sync(~0u, rs0, 2);
            rs1 += __shfl_xor_sync(~0u, rs1, 1); rs1 += __shfl_xor_sync(~0u, rs1, 2);
            lr[mt][0] += rs0; lr[mt][1] += rs1;
        }

        // O += P.V (fp16 accum); V fragments shared across both m-tiles
        #pragma unroll
        for (int kc=0;kc<4;kc++){
            #pragma unroll
            for (int dp=0;dp<4;dp++){
                uint32_t b0,b1,b2,b3;
                ldmx4t(b0,b1,b2,b3,
                       &Vs[(kc*16+((lane>>3)&1)*8+(lane&7))*72 + dp*16 + (lane>>4)*8]);
                #pragma unroll
                for (int mt=0;mt<2;mt++){
                    uint32_t pa[4] = { s2[mt][2*kc][0], s2[mt][2*kc][1],
                                       s2[mt][2*kc+1][0], s2[mt][2*kc+1][1] };
                    mmaf16(accO[mt][2*dp],   pa, b0,b1);
                    mmaf16(accO[mt][2*dp+1], pa, b2,b3);
                }
            }
        }
    }

    // epilogue: warp-private rows
    int b = bh>>3, h = bh&7;
    #pragma unroll
    for (int mt=0;mt<2;mt++){
        #pragma unroll
        for (int hh=0;hh<2;hh++){
            int row = w*32 + mt*16 + (lane>>2) + 8*hh;
            float inv = 1.f/lr[mt][hh];
            __half* orow = g_oh + (size_t)(b*NN + i0 + row)*DD + h*DH;
            float ss = 0.f;
            #pragma unroll
            for (int nt=0;nt<8;nt++){
                float2 f = __half22float2(*(__half2*)&accO[mt][nt][hh]);
                float o0 = f.x*inv, o1 = f.y*inv;
                __half2 h2 = __floats2half2_rn(o0, o1);
                *(__half2*)&orow[nt*8 + 2*(lane&3)] = h2;
                float2 rr = __half22float2(h2);
                float a0 = rr.x+32.f, a1 = rr.y+32.f;
                ss += a0*a0 + a1*a1;
            }
            ss += __shfl_xor_sync(~0u, ss, 1);
            ss += __shfl_xor_sync(~0u, ss, 2);
            if ((lane&3)==0) atomicAdd(&g_osq[b*NN + i0 + row], ss);
        }
    }
}

// ---------------- launch ----------------
extern "C" void kernel_launch(void* const* d_in, const int* in_sizes, int n_in,
                              void* d_out, int out_size) {
    const float* x    = (const float*)d_in[0];
    const float* wqkv = (const float*)d_in[1];
    const float* wout = (const float*)d_in[2];
    float* out = (float*)d_out;

    cudaFuncSetAttribute(qkv_gemm_tc, cudaFuncAttributeMaxDynamicSharedMemorySize, GSM_BYTES);
    cudaFuncSetAttribute(out_gemm_tc, cudaFuncAttributeMaxDynamicSharedMemorySize, GSM_BYTES);
    cudaFuncSetAttribute(flash_tc,    cudaFuncAttributeMaxDynamicSharedMemorySize, FSM_BYTES);

    prep_kernel<<<M_TOT + NQKV + DD, 128>>>(x, wqkv, wout);
    qkv_gemm_tc<<<dim3(NQKV/128, M_TOT/128), 128, GSM_BYTES>>>();
    flash_tc<<<dim3(NN/128, 32), 128, FSM_BYTES>>>();
    out_gemm_tc<<<dim3(DD/128, M_TOT/128), 128, GSM_BYTES>>>(out);
}

// round 14
// speedup vs baseline: 1.0097x; 1.0097x over previous
#include <cuda_runtime.h>
#include <cuda_fp16.h>
#include <math.h>
#include <stdint.h>

#define BB 4
#define HH 8
#define NN 2048
#define DD 512
#define DH 64
#define M_TOT (BB*NN)          // 8192
#define NQKV (3*DD)            // 1536
#define LOG2E 1.4426950408889634f

// ---------------- device scratch ----------------
__device__ __align__(16) __half g_xh [(size_t)M_TOT*DD];
__device__ __align__(16) __half g_wqh[(size_t)NQKV*DD];
__device__ __align__(16) __half g_woh[(size_t)DD*DD];
__device__ __align__(16) __half g_qkvh[(size_t)3*32*NN*DH];  // centered q,k,v
__device__ __align__(16) __half g_oh[(size_t)M_TOT*DD];      // centered attn out
__device__ float g_xsq[M_TOT];
__device__ float g_wqsq[NQKV];
__device__ float g_wosq[DD];
__device__ float g_wrs[DD];                          // row-sums of w_out
__device__ float g_osq[M_TOT];
__device__ __align__(16) float g_qksq[2*32*NN];      // centered |q|^2, |k|^2 per (bh,n)

// ---------------- helpers ----------------
__device__ __forceinline__ void ldmx4(uint32_t& r0,uint32_t& r1,uint32_t& r2,uint32_t& r3, const void* p){
    uint32_t a = (uint32_t)__cvta_generic_to_shared(p);
    asm volatile("ldmatrix.sync.aligned.m8n8.x4.shared.b16 {%0,%1,%2,%3}, [%4];"
        : "=r"(r0),"=r"(r1),"=r"(r2),"=r"(r3) : "r"(a));
}
__device__ __forceinline__ void ldmx4t(uint32_t& r0,uint32_t& r1,uint32_t& r2,uint32_t& r3, const void* p){
    uint32_t a = (uint32_t)__cvta_generic_to_shared(p);
    asm volatile("ldmatrix.sync.aligned.m8n8.x4.trans.shared.b16 {%0,%1,%2,%3}, [%4];"
        : "=r"(r0),"=r"(r1),"=r"(r2),"=r"(r3) : "r"(a));
}
// fp16-accumulate MMA: D,C are 2 x .f16x2 regs
__device__ __forceinline__ void mmaf16(uint32_t* c, const uint32_t* a, uint32_t b0, uint32_t b1){
    asm volatile("mma.sync.aligned.m16n8k16.row.col.f16.f16.f16.f16 "
        "{%0,%1}, {%2,%3,%4,%5}, {%6,%7}, {%0,%1};"
        : "+r"(c[0]),"+r"(c[1])
        : "r"(a[0]),"r"(a[1]),"r"(a[2]),"r"(a[3]),"r"(b0),"r"(b1));
}
__device__ __forceinline__ void cp_async16(void* dst, const void* src){
    uint32_t a = (uint32_t)__cvta_generic_to_shared(dst);
    asm volatile("cp.async.cg.shared.global [%0], [%1], 16;" :: "r"(a), "l"(src) : "memory");
}
#define CP_COMMIT  asm volatile("cp.async.commit_group;" ::: "memory")
template<int N> __device__ __forceinline__ void cp_wait(){
    asm volatile("cp.async.wait_group %0;" :: "n"(N) : "memory");
}
__device__ __forceinline__ uint32_t h2exp2(uint32_t t){
    uint32_t p; asm("ex2.approx.f16x2 %0, %1;" : "=r"(p) : "r"(t)); return p;
}

// ---------------- prep: fp16 convert + norms/rowsums, zero accumulators ----------------
__global__ void prep_kernel(const float* __restrict__ x, const float* __restrict__ wq,
                            const float* __restrict__ wo){
    int r = blockIdx.x;
    const float* src; __half* dstb; float* dsq; float* drs = nullptr;
    if (r < M_TOT)              { src = x  + (size_t)r*DD; dstb = g_xh  + (size_t)r*DD; dsq = g_xsq + r; }
    else if (r < M_TOT + NQKV)  { int rr = r - M_TOT; src = wq + (size_t)rr*DD; dstb = g_wqh + (size_t)rr*DD; dsq = g_wqsq + rr; }
    else { int rr = r - M_TOT - NQKV; src = wo + (size_t)rr*DD; dstb = g_woh + (size_t)rr*DD; dsq = g_wosq + rr; drs = g_wrs + rr; }

    if (r < 1024) g_qksq[r*128 + threadIdx.x] = 0.f;   // zero 2*32*2048 norm accumulators

    float4 v = ((const float4*)src)[threadIdx.x];
    __half2 h0 = __floats2half2_rn(v.x, v.y);
    __half2 h1 = __floats2half2_rn(v.z, v.w);
    __half2* d2 = (__half2*)(dstb + threadIdx.x*4);
    d2[0]=h0; d2[1]=h1;
    float2 f0 = __half22float2(h0), f1 = __half22float2(h1);
    float ss = f0.x*f0.x + f0.y*f0.y + f1.x*f1.x + f1.y*f1.y;
    float rs = f0.x + f0.y + f1.x + f1.y;
    #pragma unroll
    for (int o=16;o>0;o>>=1){ ss += __shfl_xor_sync(~0u, ss, o); rs += __shfl_xor_sync(~0u, rs, o); }
    __shared__ float wsum[4], wsum2[4];
    if ((threadIdx.x&31)==0){ wsum[threadIdx.x>>5]=ss; wsum2[threadIdx.x>>5]=rs; }
    __syncthreads();
    if (threadIdx.x==0){
        *dsq = wsum[0]+wsum[1]+wsum[2]+wsum[3];
        if (drs) *drs = wsum2[0]+wsum2[1]+wsum2[2]+wsum2[3];
        if (r < M_TOT) g_osq[r] = 0.f;
    }
}

// ===================== GEMMs (R12 config): CTA 128x128, warp 32x64, K-chunk 32, 3-stage ============
#define GST 20480
#define GSM_BYTES (3*GST)

// ---------------- QKV GEMM ----------------
__global__ __launch_bounds__(256,3) void qkv_gemm_tc(){
    extern __shared__ char smc[];
    int tid=threadIdx.x, lane=tid&31, wid=tid>>5;
    int wr=wid>>1, wc=wid&1;
    int m0=blockIdx.y*128, n0=blockIdx.x*128;
    uint32_t acc[2][8][2];
    #pragma unroll
    for(int i=0;i<2;i++) for(int j=0;j<8;j++){ acc[i][j][0]=0u; acc[i][j][1]=0u; }

    auto load_stage = [&](int kt, int st){
        __half* As = (__half*)(smc + st*GST);
        __half* Bs = (__half*)(smc + st*GST + 10240);
        #pragma unroll
        for (int u=0;u<2;u++){
            int idx=tid+256*u; int row=idx>>2; int q=idx&3;
            cp_async16(&As[row*40+q*8], &g_xh [(size_t)(m0+row)*DD + kt + q*8]);
            cp_async16(&Bs[row*40+q*8], &g_wqh[(size_t)(n0+row)*DD + kt + q*8]);
        }
    };
    load_stage(0, 0);  CP_COMMIT;
    load_stage(32, 1); CP_COMMIT;

    for (int it=0; it<16; it++){
        int st = it%3;
        if (it<15) cp_wait<1>(); else cp_wait<0>();
        __syncthreads();
        if (it+2 < 16){ load_stage((it+2)*32, (it+2)%3); CP_COMMIT; }
        __half* As = (__half*)(smc + st*GST);
        __half* Bs = (__half*)(smc + st*GST + 10240);
        #pragma unroll
        for (int kc=0;kc<2;kc++){
            uint32_t a[2][4];
            #pragma unroll
            for (int mt=0;mt<2;mt++)
                ldmx4(a[mt][0],a[mt][1],a[mt][2],a[mt][3],
                      &As[(wr*32+mt*16+(lane&15))*40 + kc*16 + (lane>>4)*8]);
            #pragma unroll
            for (int p=0;p<4;p++){
                uint32_t b0,b1,b2,b3;
                ldmx4(b0,b1,b2,b3,
                      &Bs[(wc*64+p*16+(lane>>4)*8+(lane&7))*40 + kc*16 + ((lane>>3)&1)*8]);
                #pragma unroll
                for (int mt=0;mt<2;mt++){
                    mmaf16(acc[mt][2*p],   a[mt], b0,b1);
                    mmaf16(acc[mt][2*p+1], a[mt], b2,b3);
                }
            }
        }
    }
    int colbase = n0 + wc*64;
    int part = colbase>>9, rem = colbase&511, h = rem>>6, dbase = rem&63;
    #pragma unroll
    for (int mt=0;mt<2;mt++){
        #pragma unroll
        for (int hh=0;hh<2;hh++){
            int m = m0 + wr*32 + mt*16 + (lane>>2) + 8*hh;
            int b = m>>11, n = m&2047;
            float xs = g_xsq[m];
            __half* orow = g_qkvh + ((size_t)(part*32 + b*8 + h)*NN + n)*DH;
            float ss = 0.f;
            #pragma unroll
            for (int nt=0;nt<8;nt++){
                int col = colbase + nt*8 + 2*(lane&3);
                float2 dd = __half22float2(*(__half2*)&acc[mt][nt][hh]);
                float v0 = sqrtf(fmaxf(xs + g_wqsq[col]   - 2.f*dd.x, 0.f)) - 32.f;
                float v1 = sqrtf(fmaxf(xs + g_wqsq[col+1] - 2.f*dd.y, 0.f)) - 32.f;
                __half2 h2 = __floats2half2_rn(v0, v1);
                *(__half2*)&orow[dbase + nt*8 + 2*(lane&3)] = h2;
                float2 rr = __half22float2(h2);           // norms from ROUNDED values
                ss += rr.x*rr.x + rr.y*rr.y;
            }
            if (part < 2){                                // q- AND k-norms
                ss += __shfl_xor_sync(~0u, ss, 1);
                ss += __shfl_xor_sync(~0u, ss, 2);
                if ((lane&3)==0) atomicAdd(&g_qksq[(part*32 + b*8 + h)*NN + n], ss);
            }
        }
    }
}

// ---------------- output GEMM ----------------
__global__ __launch_bounds__(256,3) void out_gemm_tc(float* __restrict__ out){
    extern __shared__ char smc[];
    int tid=threadIdx.x, lane=tid&31, wid=tid>>5;
    int wr=wid>>1, wc=wid&1;
    int m0=blockIdx.y*128, n0=blockIdx.x*128;
    uint32_t acc[2][8][2];
    #pragma unroll
    for(int i=0;i<2;i++) for(int j=0;j<8;j++){ acc[i][j][0]=0u; acc[i][j][1]=0u; }

    auto load_stage = [&](int kt, int st){
        __half* As = (__half*)(smc + st*GST);
        __half* Bs = (__half*)(smc + st*GST + 10240);
        #pragma unroll
        for (int u=0;u<2;u++){
            int idx=tid+256*u; int row=idx>>2; int q=idx&3;
            cp_async16(&As[row*40+q*8], &g_oh [(size_t)(m0+row)*DD + kt + q*8]);
            cp_async16(&Bs[row*40+q*8], &g_woh[(size_t)(n0+row)*DD + kt + q*8]);
        }
    };
    load_stage(0, 0);  CP_COMMIT;
    load_stage(32, 1); CP_COMMIT;

    for (int it=0; it<16; it++){
        int st = it%3;
        if (it<15) cp_wait<1>(); else cp_wait<0>();
        __syncthreads();
        if (it+2 < 16){ load_stage((it+2)*32, (it+2)%3); CP_COMMIT; }
        __half* As = (__half*)(smc + st*GST);
        __half* Bs = (__half*)(smc + st*GST + 10240);
        #pragma unroll
        for (int kc=0;kc<2;kc++){
            uint32_t a[2][4];
            #pragma unroll
            for (int mt=0;mt<2;mt++)
                ldmx4(a[mt][0],a[mt][1],a[mt][2],a[mt][3],
                      &As[(wr*32+mt*16+(lane&15))*40 + kc*16 + (lane>>4)*8]);
            #pragma unroll
            for (int p=0;p<4;p++){
                uint32_t b0,b1,b2,b3;
                ldmx4(b0,b1,b2,b3,
                      &Bs[(wc*64+p*16+(lane>>4)*8+(lane&7))*40 + kc*16 + ((lane>>3)&1)*8]);
                #pragma unroll
                for (int mt=0;mt<2;mt++){
                    mmaf16(acc[mt][2*p],   a[mt], b0,b1);
                    mmaf16(acc[mt][2*p+1], a[mt], b2,b3);
                }
            }
        }
    }
    #pragma unroll
    for (int mt=0;mt<2;mt++){
        #pragma unroll
        for (int hh=0;hh<2;hh++){
            int m = m0 + wr*32 + mt*16 + (lane>>2) + 8*hh;
            float os = g_osq[m];
            #pragma unroll
            for (int nt=0;nt<8;nt++){
                int col = n0 + wc*64 + nt*8 + 2*(lane&3);
                float2 dd = __half22float2(*(__half2*)&acc[mt][nt][hh]);
                float dot0 = dd.x + 32.f*g_wrs[col];
                float dot1 = dd.y + 32.f*g_wrs[col+1];
                out[(size_t)m*DD + col]   = sqrtf(fmaxf(os + g_wosq[col]   - 2.f*dot0, 0.f));
                out[(size_t)m*DD + col+1] = sqrtf(fmaxf(os + g_wosq[col+1] - 2.f*dot1, 0.f));
            }
        }
    }
}

// ---------- flash: 256 thr, 8 warps = 4 m-warps x 2 j-half warps, fp16, 3-stage ring ----------
// smem: Qs [128][72] = 18432 | stage s at 18432+s*18688: K(9216) V(9216) ksq(256)
// merge area (post-loop, reuses stages): accO halves 16KB @18432, lr 512B @34816
#define FSTAGE 18688
#define FSM_BYTES (18432 + 3*FSTAGE)
__global__ __launch_bounds__(256,2) void flash_tc(){
    extern __shared__ char smem[];
    __half* Qs = (__half*)smem;

    int tid=threadIdx.x, lane=tid&31, w=tid>>5;
    int wr=w>>1, wc=w&1;                 // wr: m-quarter (32 rows), wc: j-half (32 of 64)
    int bh = blockIdx.y; int i0 = blockIdx.x*128;
    const __half* qg = g_qkvh + ((size_t)(0*32+bh)*NN + i0)*DH;
    const __half* kg = g_qkvh + (size_t)(1*32+bh)*NN*DH;
    const __half* vg = g_qkvh + (size_t)(2*32+bh)*NN*DH;
    const float* qsqg = g_qksq + (size_t)(0*32+bh)*NN + i0;
    const float* ksqg = g_qksq + (size_t)(1*32+bh)*NN;

    auto load_stage = [&](int j0, int st){
        char* base = smem + 18432 + st*FSTAGE;
        __half* Ks = (__half*)base;
        __half* Vs = (__half*)(base + 9216);
        float* kq = (float*)(base + 18432);
        #pragma unroll
        for (int u=0;u<2;u++){
            int idx=tid+256*u; int row=idx>>3; int q=idx&7;
            cp_async16(&Ks[row*72+q*8], &kg[(size_t)(j0+row)*DH+q*8]);
            cp_async16(&Vs[row*72+q*8], &vg[(size_t)(j0+row)*DH+q*8]);
        }
        if (tid<16) cp_async16(&kq[tid*4], &ksqg[j0+tid*4]);
    };

    #pragma unroll
    for (int u=0;u<4;u++){
        int idx=tid+256*u; int row=idx>>3; int q=idx&7;
        cp_async16(&Qs[row*72+q*8], &qg[(size_t)row*DH + q*8]);
    }
    CP_COMMIT;
    load_stage(0, 0);  CP_COMMIT;
    load_stage(64, 1); CP_COMMIT;

    cp_wait<2>();
    __syncthreads();

    // hoist Q fragments: warp (wr) owns rows [32wr, 32wr+32): two 16-row m-tiles
    uint32_t qf[2][4][4];
    #pragma unroll
    for (int mt=0;mt<2;mt++)
        #pragma unroll
        for (int kc=0;kc<4;kc++)
            ldmx4(qf[mt][kc][0],qf[mt][kc][1],qf[mt][kc][2],qf[mt][kc][3],
                  &Qs[(wr*32+mt*16+(lane&15))*72 + kc*16 + (lane>>4)*8]);

    const float C2 = 0.125f*LOG2E;
    const float BIAS = 12.0f;                 // logit = BIAS - C2*d^2 <= BIAS -> p <= 4096 (fp16-safe)
    const __half2 C1h = __float2half2_rn(0.25f*LOG2E);
    float rowc[2][2];
    #pragma unroll
    for (int mt=0;mt<2;mt++){
        rowc[mt][0] = BIAS - C2*qsqg[wr*32 + mt*16 + (lane>>2)];
        rowc[mt][1] = BIAS - C2*qsqg[wr*32 + mt*16 + (lane>>2) + 8];
    }

    float lr[2][2] = {{0.f,0.f},{0.f,0.f}};   // partial over this warp's j-half
    uint32_t accO[2][8][2];                   // partial over this warp's j-half, full 64 d
    #pragma unroll
    for (int mt=0;mt<2;mt++) for (int j=0;j<8;j++){ accO[mt][j][0]=0u; accO[mt][j][1]=0u; }

    for (int t=0; t<32; t++){
        int st = t%3;
        if (t<31) cp_wait<1>(); else cp_wait<0>();
        __syncthreads();
        if (t+2 < 32){ load_stage((t+2)*64, (t+2)%3); CP_COMMIT; }
        char* base = smem + 18432 + st*FSTAGE;
        __half* Ks = (__half*)base;
        __half* Vs = (__half*)(base + 9216);
        const float* ksq = (const float*)(base + 18432);

        // S = Q.K^T over this warp's 32-j half; K fragments shared by 4 m-warps (not 8)
        uint32_t s2[2][4][2];
        #pragma unroll
        for(int mt=0;mt<2;mt++) for(int j=0;j<4;j++){ s2[mt][j][0]=0u; s2[mt][j][1]=0u; }
        #pragma unroll
        for (int kc=0;kc<4;kc++){
            #pragma unroll
            for (int p=0;p<2;p++){
                uint32_t b0,b1,b2,b3;
                ldmx4(b0,b1,b2,b3,
                      &Ks[(wc*32+p*16+(lane>>4)*8+(lane&7))*72 + kc*16 + ((lane>>3)&1)*8]);
                #pragma unroll
                for (int mt=0;mt<2;mt++){
                    mmaf16(s2[mt][2*p],   qf[mt][kc], b0,b1);
                    mmaf16(s2[mt][2*p+1], qf[mt][kc], b2,b3);
                }
            }
        }

        // p = exp2(C1*s + rowc - C2*|k|^2); result IS the PV A-fragment
        #pragma unroll
        for (int mt=0;mt<2;mt++){
            __half2 hs0 = __float2half2_rn(0.f), hs1 = __float2half2_rn(0.f);
            #pragma unroll
            for (int nt=0;nt<4;nt++){
                float2 kf = *(const float2*)&ksq[wc*32 + nt*8 + 2*(lane&3)];
                __half2 c0 = __floats2half2_rn(rowc[mt][0] - C2*kf.x, rowc[mt][0] - C2*kf.y);
                __half2 c1 = __floats2half2_rn(rowc[mt][1] - C2*kf.x, rowc[mt][1] - C2*kf.y);
                __half2 t0 = __hfma2(*(__half2*)&s2[mt][nt][0], C1h, c0);
                __half2 t1 = __hfma2(*(__half2*)&s2[mt][nt][1], C1h, c1);
                s2[mt][nt][0] = h2exp2(*(uint32_t*)&t0);
                s2[mt][nt][1] = h2exp2(*(uint32_t*)&t1);
                hs0 = __hadd2(hs0, *(__half2*)&s2[mt][nt][0]);
                hs1 = __hadd2(hs1, *(__half2*)&s2[mt][nt][1]);
            }
            float2 f0 = __half22float2(hs0), f1 = __half22float2(hs1);
            float rs0 = f0.x + f0.y, rs1 = f1.x + f1.y;
            rs0 += __shfl_xor_sync(~0u, rs0, 1); rs0 += __shfl_xor_sync(~0u, rs0, 2);
            rs1 += __shfl_xor_sync(~0u, rs1, 1); rs1 += __shfl_xor_sync(~0u, rs1, 2);
            lr[mt][0] += rs0; lr[mt][1] += rs1;
        }

        // O += P.V over this warp's 32-j half (2 k-chunks); V fragments shared by 4 m-warps
        #pragma unroll
        for (int kc=0;kc<2;kc++){
            #pragma unroll
            for (int dp=0;dp<4;dp++){
                uint32_t b0,b1,b2,b3;
                ldmx4t(b0,b1,b2,b3,
                       &Vs[(wc*32+kc*16+((lane>>3)&1)*8+(lane&7))*72 + dp*16 + (lane>>4)*8]);
                #pragma unroll
                for (int mt=0;mt<2;mt++){
                    uint32_t pa[4] = { s2[mt][2*kc][0], s2[mt][2*kc][1],
                                       s2[mt][2*kc+1][0], s2[mt][2*kc+1][1] };
                    mmaf16(accO[mt][2*dp],   pa, b0,b1);
                    mmaf16(accO[mt][2*dp+1], pa, b2,b3);
                }
            }
        }
    }

    // merge the two j-halves (plain sums through smem), then finalize
    __syncthreads();
    uint32_t* sO = (uint32_t*)(smem + 18432);        // [128 rows][32 half2]
    float* sl    = (float*)(smem + 18432 + 16384);   // [128]
    if (wc==1){
        #pragma unroll
        for (int mt=0;mt<2;mt++)
        #pragma unroll
        for (int hh=0;hh<2;hh++){
            int row = wr*32 + mt*16 + (lane>>2) + 8*hh;
            if ((lane&3)==0) sl[row] = lr[mt][hh];
            #pragma unroll
            for (int nt=0;nt<8;nt++)
                sO[row*32 + nt*4 + (lane&3)] = accO[mt][nt][hh];
        }
    }
    __syncthreads();
    if (wc==0){
        int b = bh>>3, h = bh&7;
        #pragma unroll
        for (int mt=0;mt<2;mt++)
        #pragma unroll
        for (int hh=0;hh<2;hh++){
            int row = wr*32 + mt*16 + (lane>>2) + 8*hh;
            float inv = 1.f/(lr[mt][hh] + sl[row]);
            __half* orow = g_oh + (size_t)(b*NN + i0 + row)*DD + h*DH;
            float ss = 0.f;
            #pragma unroll
            for (int nt=0;nt<8;nt++){
                float2 f0 = __half22float2(*(__half2*)&accO[mt][nt][hh]);
                float2 f1 = __half22float2(*(__half2*)&sO[row*32 + nt*4 + (lane&3)]);
                float o0 = (f0.x + f1.x)*inv, o1 = (f0.y + f1.y)*inv;
                __half2 h2 = __floats2half2_rn(o0, o1);
                *(__half2*)&orow[nt*8 + 2*(lane&3)] = h2;
                float2 rr = __half22float2(h2);
                float a0 = rr.x+32.f, a1 = rr.y+32.f;
                ss += a0*a0 + a1*a1;
            }
            ss += __shfl_xor_sync(~0u, ss, 1);
            ss += __shfl_xor_sync(~0u, ss, 2);
            if ((lane&3)==0) atomicAdd(&g_osq[b*NN + i0 + row], ss);
        }
    }
}

// ---------------- launch ----------------
extern "C" void kernel_launch(void* const* d_in, const int* in_sizes, int n_in,
                              void* d_out, int out_size) {
    const float* x    = (const float*)d_in[0];
    const float* wqkv = (const float*)d_in[1];
    const float* wout = (const float*)d_in[2];
    float* out = (float*)d_out;

    cudaFuncSetAttribute(qkv_gemm_tc, cudaFuncAttributeMaxDynamicSharedMemorySize, GSM_BYTES);
    cudaFuncSetAttribute(out_gemm_tc, cudaFuncAttributeMaxDynamicSharedMemorySize, GSM_BYTES);
    cudaFuncSetAttribute(flash_tc,    cudaFuncAttributeMaxDynamicSharedMemorySize, FSM_BYTES);

    prep_kernel<<<M_TOT + NQKV + DD, 128>>>(x, wqkv, wout);
    qkv_gemm_tc<<<dim3(NQKV/128, M_TOT/128), 256, GSM_BYTES>>>();
    flash_tc<<<dim3(NN/128, 32), 256, FSM_BYTES>>>();
    out_gemm_tc<<<dim3(DD/128, M_TOT/128), 256, GSM_BYTES>>>(out);
}